// round 4
// baseline (speedup 1.0000x reference)
#include <cuda_runtime.h>
#include <math.h>

// Problem constants
#define LS    32
#define SEQL  1024
#define BSZ   8
#define EMBED 1024
#define KDIM  64
#define NDIM  16
#define VPOW  64
#define RTOT  16384
#define R2    16

// ---------------- scratch (__device__ globals; no allocation anywhere) -------
__device__ float         g_Apow[4 * VPOW * 1024];   // [a][v][kd*16+n]
__device__ float         g_Bsig[2 * 1024];          // [col][kd*16+n]
__device__ unsigned char g_idx8[2 * 4 * RTOT];      // [d][a][r]
__device__ float         g_coef[2 * RTOT];          // signed: +coef->col0, -coef->col1
__device__ float         g_w[2 * 1024 * 1024];      // [d][p][kd*16+n]
__device__ float         g_kk[1024 * 4096];         // [p][kd*64+h]
__device__ float         g_ksum[1024 * 1024];       // [p*32+q][e]

// ---------------- 1. sigmoid + power tables ---------------------------------
__global__ void k_setup(const float* __restrict__ A,
                        const float* __restrict__ B1,
                        const float* __restrict__ B2) {
    int id = blockIdx.x * 256 + threadIdx.x;
    if (id < 4096) {
        float s = 1.f / (1.f + expf(-A[id]));
        int a = id >> 10, t = id & 1023;
        float cur = 1.f;
        #pragma unroll
        for (int v = 0; v < VPOW; v++) {
            g_Apow[(a * VPOW + v) * 1024 + t] = cur;
            cur *= s;
        }
    } else if (id < 4096 + 2048) {
        int j = id - 4096;
        const float* B = (j < 1024) ? B1 : B2;
        g_Bsig[j] = 1.f / (1.f + expf(-B[j & 1023]));
    }
}

// ---------------- 2. one-hot index extraction from one_matrix ---------------
__global__ void k_extract(const float* __restrict__ OM) {
    int gwarp = (blockIdx.x * 256 + threadIdx.x) >> 5;
    int lane  = threadIdx.x & 31;
    // gwarp in [0, 2*5*RTOT)
    int d   = gwarp / (5 * RTOT);
    int rem = gwarp - d * 5 * RTOT;
    int a   = rem / RTOT;
    int r   = rem - a * RTOT;
    int base = ((d * 5 + a) * RTOT + r) * VPOW;
    float v0 = OM[base + lane];
    float v1 = OM[base + 32 + lane];
    unsigned m0 = __ballot_sync(0xffffffffu, v0 != 0.f);
    unsigned m1 = __ballot_sync(0xffffffffu, v1 != 0.f);
    int idx = m0 ? (__ffs(m0) - 1) : (32 + __ffs(m1) - 1);
    if (a < 4) {
        if (lane == 0) g_idx8[(d * 4 + a) * RTOT + r] = (unsigned char)idx;
    } else {
        float val = __shfl_sync(0xffffffffu, (idx < 32) ? v0 : v1, idx & 31);
        if (lane == 0) g_coef[d * RTOT + r] = (idx == 0) ? val : -val;
    }
}

// ---------------- 3. w[d][p][kd*16+n] ---------------------------------------
__global__ void k_w() {
    int p = blockIdx.x, d = blockIdx.y, t = threadIdx.x;
    float b0 = g_Bsig[t];
    float b1 = g_Bsig[1024 + t];
    float acc = 0.f;
    int rbase = p * 16;
    #pragma unroll
    for (int r2 = 0; r2 < R2; r2++) {
        int r  = rbase + r2;
        int i0 = g_idx8[(d * 4 + 0) * RTOT + r];
        int i1 = g_idx8[(d * 4 + 1) * RTOT + r];
        int i2 = g_idx8[(d * 4 + 2) * RTOT + r];
        int i3 = g_idx8[(d * 4 + 3) * RTOT + r];
        float cf = g_coef[d * RTOT + r];
        float term = g_Apow[(0 * VPOW + i0) * 1024 + t]
                   * g_Apow[(1 * VPOW + i1) * 1024 + t]
                   * g_Apow[(2 * VPOW + i2) * 1024 + t]
                   * g_Apow[(3 * VPOW + i3) * 1024 + t];
        acc += term * fabsf(cf) * ((cf > 0.f) ? b0 : b1);
    }
    g_w[(d * 1024 + p) * 1024 + t] = acc;
}

// ---------------- 4. kk[p][kd*64+h] = sum_{d,n} w * C/4 ---------------------
__global__ void k_kk(const float* __restrict__ C1, const float* __restrict__ C2) {
    __shared__ float Csh[2048];                     // [d][h][n]
    int kd = blockIdx.x, pc = blockIdx.y, tid = threadIdx.x;
    for (int idx = tid; idx < 2048; idx += 256) {
        int d = idx >> 10, rem = idx & 1023, h = rem >> 4, n = rem & 15;
        const float* C = d ? C2 : C1;
        Csh[idx] = C[(h * 64 + kd) * 16 + n] * 0.25f;
    }
    __syncthreads();
    int h = tid & 63, pr = tid >> 6;               // 4 p-rows per pass
    for (int pl = 0; pl < 16; pl++) {
        int p = pc * 64 + pl * 4 + pr;
        const float* w0 = &g_w[(0 * 1024 + p) * 1024 + kd * 16];
        const float* w1 = &g_w[(1 * 1024 + p) * 1024 + kd * 16];
        float acc = 0.f;
        #pragma unroll
        for (int n = 0; n < NDIM; n++) {
            acc = fmaf(w0[n], Csh[h * 16 + n], acc);
            acc = fmaf(w1[n], Csh[1024 + h * 16 + n], acc);
        }
        g_kk[p * 4096 + kd * 64 + h] = acc;        // coalesced over h
    }
}

// ---------------- 5. direction flips + boundary scaling → ksum[p][e] --------
__device__ __forceinline__ float bfactor(int a, int b) {
    float f = 1.f;
    if (a == 0) f *= 2.f;
    if (b == 0) f *= 2.f;
    if (a == 0 && b == 0) f *= 0.25f;
    return f;
}

__global__ void k_ksum() {
    __shared__ float sh[4][1024];                  // per-dir [s*64+h] slice
    int pi = blockIdx.x, pj = blockIdx.y, tid = threadIdx.x;
    int rows[4] = { pi * 32 + pj, (31 - pi) * 32 + pj,
                    pi * 32 + (31 - pj), (31 - pi) * 32 + (31 - pj) };
    #pragma unroll
    for (int dir = 0; dir < 4; dir++)
        for (int idx = tid; idx < 1024; idx += 256)
            sh[dir][idx] = g_kk[rows[dir] * 4096 + dir * 1024 + idx];
    __syncthreads();
    float f0 = bfactor(pi, pj), f1 = bfactor(31 - pi, pj);
    float f2 = bfactor(pi, 31 - pj), f3 = bfactor(31 - pi, 31 - pj);
    for (int e = tid; e < 1024; e += 256) {
        int h = e >> 4, s = e & 15;
        int o = s * 64 + h;
        float v = f0 * sh[0][o] + f1 * sh[1][o] + f2 * sh[2][o] + f3 * sh[3][o];
        g_ksum[(pi * 32 + pj) * 1024 + e] = v;
    }
}

// ---------------- 6. triangular direct conv + residual ----------------------
__global__ void __launch_bounds__(256, 1)
k_conv(const float* __restrict__ x, const float* __restrict__ omega,
       float* __restrict__ out) {
    int e = blockIdx.x * 256 + threadIdx.x;
    int i = blockIdx.y;
    int b = blockIdx.z;
    const float* xb = x + b * 1024 + e;            // l-stride 8192 floats

    float acc[32];
    #pragma unroll
    for (int j = 0; j < 32; j++) acc[j] = 0.f;
    float xr[32];

    for (int u = 0; u <= i; u++) {
        int p = i - u;
        const float* xrow = xb + (u * 32) * 8192;
        #pragma unroll
        for (int j = 0; j < 32; j++) xr[j] = xrow[j * 8192];
        float kr[32];
        const float* krow = g_ksum + (p * 32) * 1024 + e;
        #pragma unroll
        for (int q = 0; q < 32; q++) kr[q] = krow[q * 1024];
        #pragma unroll
        for (int j = 0; j < 32; j++) {
            #pragma unroll
            for (int q = 0; q <= j; q++)
                acc[j] = fmaf(kr[q], xr[j - q], acc[j]);
        }
    }
    // xr now holds input row i (u == i on last iteration) -> residual
    float om = omega[e];
    float* ob = out + b * 1024 + e;
    #pragma unroll
    for (int j = 0; j < 32; j++)
        ob[(i * 32 + j) * 8192] = acc[j] + xr[j] * om;
}

// ---------------- launch -----------------------------------------------------
extern "C" void kernel_launch(void* const* d_in, const int* in_sizes, int n_in,
                              void* d_out, int out_size) {
    const float* x   = (const float*)d_in[0];
    const float* A   = (const float*)d_in[1];
    const float* B1  = (const float*)d_in[2];
    const float* B2  = (const float*)d_in[3];
    const float* C1  = (const float*)d_in[4];
    const float* C2  = (const float*)d_in[5];
    const float* om  = (const float*)d_in[6];
    const float* OM  = (const float*)d_in[7];
    float* out = (float*)d_out;

    k_setup<<<24, 256>>>(A, B1, B2);
    k_extract<<<(2 * 5 * RTOT) / 8, 256>>>(OM);    // 8 warps/block, exact
    k_w<<<dim3(1024, 2), 1024>>>();
    k_kk<<<dim3(64, 16), 256>>>(C1, C2);
    k_ksum<<<dim3(32, 32), 256>>>();
    k_conv<<<dim3(4, 32, 8), 256>>>(x, om, out);
}